// round 13
// baseline (speedup 1.0000x reference)
#include <cuda_runtime.h>
#include <cuda_fp16.h>
#include <cstdint>
#include <math.h>

#define NNODES 50000
#define RREL 3
#define EEDGE 50000
#define WTOTAL 1302528  // 3*(512*512 + 512*256 + 256*128 + 128*64)

// ---------------- scratch (device globals; no allocation allowed) ----------
__device__ float  g_hB[(size_t)NNODES * 64];      // fp32 final layer out (MLP input)
__device__ __half g_hrh[(size_t)NNODES * 1536];   // fp16 GEMM out [N, 3*dout]
__device__ __half g_xh[(size_t)NNODES * 512];     // fp16 layer-0 A
__device__ __half g_hH[(size_t)NNODES * 512];     // fp16 A for layers 1..3
__device__ __half g_Bch[WTOTAL];                  // fp16 packed weights [K, 3*dout]
__device__ float  g_sn[RREL * NNODES];            // raw out-degrees
__device__ float  g_dn[RREL * NNODES];            // raw in-degrees
__device__ int    g_off[RREL * (NNODES + 1)];     // CSR offsets by dst
__device__ int    g_cur[RREL * NNODES];           // fill cursors
__device__ int    g_esrc[RREL * EEDGE];           // CSR edge src
__device__ float  g_ecoef[RREL * EEDGE];          // CSR edge coef

// ---------------- helpers ---------------------------------------------------
__device__ __forceinline__ uint32_t smem_u32(const void* p) {
    uint32_t a;
    asm("{ .reg .u64 t; cvta.to.shared.u64 t, %1; cvt.u32.u64 %0, t; }" : "=r"(a) : "l"(p));
    return a;
}
__device__ __forceinline__ void cp_async16(uint32_t dst, const void* src, bool pred) {
    int b = pred ? 16 : 0;
    asm volatile("cp.async.cg.shared.global [%0], [%1], 16, %2;\n"
                 :: "r"(dst), "l"(src), "r"(b));
}
#define CP_COMMIT() asm volatile("cp.async.commit_group;\n" ::: "memory")
#define CP_WAIT(n)  asm volatile("cp.async.wait_group %0;\n" :: "n"(n) : "memory")

__device__ __forceinline__ void ldsm_x4(uint32_t& r0, uint32_t& r1, uint32_t& r2,
                                        uint32_t& r3, uint32_t addr) {
    asm volatile("ldmatrix.sync.aligned.m8n8.x4.shared.b16 {%0,%1,%2,%3}, [%4];"
                 : "=r"(r0), "=r"(r1), "=r"(r2), "=r"(r3) : "r"(addr));
}
__device__ __forceinline__ void ldsm_x4_t(uint32_t& r0, uint32_t& r1, uint32_t& r2,
                                          uint32_t& r3, uint32_t addr) {
    asm volatile("ldmatrix.sync.aligned.m8n8.x4.trans.shared.b16 {%0,%1,%2,%3}, [%4];"
                 : "=r"(r0), "=r"(r1), "=r"(r2), "=r"(r3) : "r"(addr));
}
__device__ __forceinline__ void mma_f16(float c[4], const uint32_t a[4], const uint32_t b[2]) {
    asm volatile(
        "mma.sync.aligned.m16n8k16.row.col.f32.f16.f16.f32 "
        "{%0,%1,%2,%3}, {%4,%5,%6,%7}, {%8,%9}, {%0,%1,%2,%3};\n"
        : "+f"(c[0]), "+f"(c[1]), "+f"(c[2]), "+f"(c[3])
        : "r"(a[0]), "r"(a[1]), "r"(a[2]), "r"(a[3]), "r"(b[0]), "r"(b[1]));
}

// ---------------- small utility kernels ------------------------------------
__global__ void zero2_kernel(float* __restrict__ a, float* __restrict__ b, int n) {
    int i = blockIdx.x * blockDim.x + threadIdx.x;
    if (i < n) { a[i] = 0.0f; b[i] = 0.0f; }
}

__global__ void round_half_kernel(const float* __restrict__ in, __half* __restrict__ out, int n) {
    int i = blockIdx.x * blockDim.x + threadIdx.x;
    if (i < n) out[i] = __float2half_rn(in[i]);
}

// pack W[r, k, c] -> Bch[k, r*dout + c] fp16. [K, Ncat] row-major.
__global__ void pack_w_kernel(const float* __restrict__ W, __half* __restrict__ out,
                              int din, int dout) {
    int i = blockIdx.x * blockDim.x + threadIdx.x;
    int Ncat = RREL * dout;
    int total = din * Ncat;
    if (i >= total) return;
    int k = i / Ncat;
    int n = i - k * Ncat;
    int r = n / dout;
    int c = n - r * dout;
    out[i] = __float2half_rn(W[((size_t)r * din + k) * dout + c]);
}

__global__ void deg_kernel(const int* __restrict__ src, const int* __restrict__ dst,
                           float* __restrict__ outdeg, float* __restrict__ indeg,
                           int E, int N) {
    int i = blockIdx.x * blockDim.x + threadIdx.x;
    if (i < RREL * E) {
        int r = i / E;
        atomicAdd(&outdeg[r * N + src[i]], 1.0f);
        atomicAdd(&indeg[r * N + dst[i]], 1.0f);
    }
}

// per-relation exclusive prefix scan, shuffle-based. 3 blocks x 1024.
__global__ void scan_kernel(const float* __restrict__ dn, int* __restrict__ off,
                            int* __restrict__ cur, int N) {
    int r = blockIdx.x;
    const float* c = dn + r * N;
    int* o = off + r * (N + 1);
    int* q = cur + r * N;
    int tid = threadIdx.x;
    int lane = tid & 31;
    int wid = tid >> 5;
    __shared__ int wsum[32];
    __shared__ int carry_s;
    if (tid == 0) carry_s = 0;
    __syncthreads();
    for (int base = 0; base < N; base += 1024) {
        int i = base + tid;
        int v = (i < N) ? (int)c[i] : 0;
        int x = v;
#pragma unroll
        for (int d = 1; d < 32; d <<= 1) {
            int t = __shfl_up_sync(0xFFFFFFFF, x, d);
            if (lane >= d) x += t;
        }
        if (lane == 31) wsum[wid] = x;
        __syncthreads();
        if (wid == 0) {
            int s = wsum[lane];
#pragma unroll
            for (int d = 1; d < 32; d <<= 1) {
                int t = __shfl_up_sync(0xFFFFFFFF, s, d);
                if (lane >= d) s += t;
            }
            wsum[lane] = s;
        }
        __syncthreads();
        int warpoff = (wid > 0) ? wsum[wid - 1] : 0;
        int excl = carry_s + warpoff + x - v;
        if (i < N) { o[i] = excl; q[i] = excl; }
        int total = wsum[31];
        __syncthreads();
        if (tid == 0) carry_s += total;
        __syncthreads();
    }
    if (tid == 0) o[N] = carry_s;
}

// scatter edges into CSR slots; coef computed inline from raw degrees
__global__ void fill_kernel(const int* __restrict__ src, const int* __restrict__ dst,
                            const float* __restrict__ sn, const float* __restrict__ dn,
                            int* __restrict__ cur, int* __restrict__ esrc,
                            float* __restrict__ ecoef, int E, int N) {
    int i = blockIdx.x * blockDim.x + threadIdx.x;
    if (i >= RREL * E) return;
    int r = i / E;
    int s = src[i], d = dst[i];
    int pos = atomicAdd(&cur[r * N + d], 1);
    esrc[r * E + pos] = s;
    ecoef[r * E + pos] = rsqrtf(fmaxf(sn[r * N + s], 1.0f)) *
                         rsqrtf(fmaxf(dn[r * N + d], 1.0f));
}

// ---------------- fp16 tensor-core GEMM, 64x64 warp tiles -------------------
// C[M,Nc](fp16) = A[M,K](fp16) @ B[K,Nc](fp16), fp32 accum.
// BM=256, BN=128, BK=64, 8 warps (4M x 2N), warp tile 64x64 = 4x8 m16n8k16.
#define BM 256
#define BN 128
#define BK 64
#define STAGES 3
#define ASTR 72     // halfs per A smem row (144 B)
#define BSTR 136    // halfs per B smem row (272 B)
#define A_STAGE_H (BM * ASTR)          // 18432 halfs
#define B_STAGE_H (BK * BSTR)          // 8704 halfs
#define STAGE_HALFS (A_STAGE_H + B_STAGE_H)
#define GEMM_SMEM_BYTES (STAGES * STAGE_HALFS * 2)   // 162816

__device__ __forceinline__ void issue_stage_loads(
    uint32_t sAs, uint32_t sBs,
    const __half* __restrict__ A, const __half* __restrict__ B,
    int M, int K, int Nc, int rowBase, int colBase, int k0, int tid) {
    // A: 256 rows x 64 halfs = 2048 x 16B ops, 8 per thread
#pragma unroll
    for (int t = 0; t < 8; t++) {
        int i  = tid + t * 256;
        int r  = i >> 3;            // 0..255
        int kc = (i & 7) << 3;      // 0..56 halfs
        int gr = rowBase + r;
        cp_async16(sAs + (uint32_t)(r * ASTR + kc) * 2,
                   A + (size_t)gr * K + k0 + kc, gr < M);
    }
    // B: 64 rows x 128 halfs = 1024 x 16B ops, 4 per thread
#pragma unroll
    for (int t = 0; t < 4; t++) {
        int i  = tid + t * 256;
        int kr = i >> 4;            // 0..63
        int nc = (i & 15) << 3;     // 0..120 halfs
        cp_async16(sBs + (uint32_t)(kr * BSTR + nc) * 2,
                   B + (size_t)(k0 + kr) * Nc + colBase + nc, colBase + nc < Nc);
    }
}

__global__ void __launch_bounds__(256, 1) gemm_f16_kernel(
    const __half* __restrict__ A, const __half* __restrict__ B,
    __half* __restrict__ C, int M, int K, int Nc) {
    extern __shared__ __half smemh[];
    uint32_t sA[STAGES], sB[STAGES];
#pragma unroll
    for (int s = 0; s < STAGES; s++) {
        sA[s] = smem_u32(smemh + (size_t)s * STAGE_HALFS);
        sB[s] = sA[s] + A_STAGE_H * 2;
    }

    const int tid    = threadIdx.x;
    const int warpId = tid >> 5;
    const int lane   = tid & 31;
    const int g      = lane >> 2;
    const int tig    = lane & 3;
    const int wm     = warpId & 3;   // 0..3 -> M offset wm*64
    const int wn     = warpId >> 2;  // 0..1 -> N offset wn*64
    const int rowBase = blockIdx.y * BM;
    const int colBase = blockIdx.x * BN;

    float acc[4][8][4];
#pragma unroll
    for (int mm = 0; mm < 4; mm++)
#pragma unroll
        for (int nn = 0; nn < 8; nn++)
#pragma unroll
            for (int i = 0; i < 4; i++) acc[mm][nn][i] = 0.0f;

    const int a_row = (lane & 15);
    const int a_sel = (lane >> 4) << 3;
    const int b_krow = (lane & 7) + (((lane >> 3) & 1) << 3);
    const int b_nsel = (lane >> 4) << 3;

    const int nk = K >> 6;   // BK=64 chunks
    issue_stage_loads(sA[0], sB[0], A, B, M, K, Nc, rowBase, colBase, 0, tid);
    CP_COMMIT();
    if (nk > 1) {
        issue_stage_loads(sA[1], sB[1], A, B, M, K, Nc, rowBase, colBase, 64, tid);
    }
    CP_COMMIT();

    int buf = 0;
    for (int i = 0; i < nk; i++) {
        if (i + 1 < nk) { CP_WAIT(1); } else { CP_WAIT(0); }
        __syncthreads();

        if (i + 2 < nk) {
            int nb = buf + 2; if (nb >= STAGES) nb -= STAGES;
            issue_stage_loads(sA[nb], sB[nb], A, B, M, K, Nc,
                              rowBase, colBase, (i + 2) << 6, tid);
            CP_COMMIT();
        }

        uint32_t sa = sA[buf], sb = sB[buf];
#pragma unroll
        for (int ks = 0; ks < BK; ks += 16) {
            uint32_t a[4][4], b[8][2];
#pragma unroll
            for (int mm = 0; mm < 4; mm++) {
                uint32_t ad = sa + (uint32_t)((wm * 64 + mm * 16 + a_row) * ASTR + ks + a_sel) * 2;
                ldsm_x4(a[mm][0], a[mm][1], a[mm][2], a[mm][3], ad);
            }
#pragma unroll
            for (int np = 0; np < 4; np++) {
                uint32_t bd = sb + (uint32_t)((ks + b_krow) * BSTR + wn * 64 + np * 16 + b_nsel) * 2;
                uint32_t t0, t1, t2, t3;
                ldsm_x4_t(t0, t1, t2, t3, bd);
                b[np * 2][0] = t0; b[np * 2][1] = t1;
                b[np * 2 + 1][0] = t2; b[np * 2 + 1][1] = t3;
            }
#pragma unroll
            for (int mm = 0; mm < 4; mm++)
#pragma unroll
                for (int nn = 0; nn < 8; nn++)
                    mma_f16(acc[mm][nn], a[mm], b[nn]);
        }
        buf++; if (buf >= STAGES) buf -= STAGES;
    }

#pragma unroll
    for (int mm = 0; mm < 4; mm++) {
        int r0 = rowBase + wm * 64 + mm * 16 + g;
#pragma unroll
        for (int nn = 0; nn < 8; nn++) {
            int c = colBase + wn * 64 + nn * 8 + tig * 2;
            if (c < Nc) {
                if (r0 < M)
                    *(__half2*)(C + (size_t)r0 * Nc + c) =
                        __floats2half2_rn(acc[mm][nn][0], acc[mm][nn][1]);
                if (r0 + 8 < M)
                    *(__half2*)(C + (size_t)(r0 + 8) * Nc + c) =
                        __floats2half2_rn(acc[mm][nn][2], acc[mm][nn][3]);
            }
        }
    }
}

// ---------------- CSR gather: bias + aggregate + relu + write ---------------
__global__ void gather_kernel(const __half* __restrict__ hr,
                              const int* __restrict__ off, const int* __restrict__ esrc,
                              const float* __restrict__ ecoef,
                              const float* __restrict__ b,
                              __half* __restrict__ outH, float* __restrict__ outF,
                              int N, int E, int dout, int do_relu) {
    int dout8 = dout >> 3;
    int idx = blockIdx.x * blockDim.x + threadIdx.x;
    if (idx >= N * dout8) return;
    int d  = idx / dout8;
    int c8 = (idx - d * dout8) << 3;
    int Ncat = RREL * dout;

    float acc[8];
#pragma unroll
    for (int j = 0; j < 8; j++)
        acc[j] = b[c8 + j] + b[dout + c8 + j] + b[2 * dout + c8 + j];

#pragma unroll
    for (int r = 0; r < RREL; r++) {
        int beg = off[r * (N + 1) + d];
        int end = off[r * (N + 1) + d + 1];
        for (int i = beg; i < end; i++) {
            int s = esrc[r * E + i];
            float cf = ecoef[r * E + i];
            const __half* p = hr + (size_t)s * Ncat + r * dout + c8;
            uint4 u = *(const uint4*)p;
            __half2 h0 = *(__half2*)&u.x, h1 = *(__half2*)&u.y;
            __half2 h2 = *(__half2*)&u.z, h3 = *(__half2*)&u.w;
            float2 f0 = __half22float2(h0), f1 = __half22float2(h1);
            float2 f2 = __half22float2(h2), f3 = __half22float2(h3);
            acc[0] = fmaf(cf, f0.x, acc[0]); acc[1] = fmaf(cf, f0.y, acc[1]);
            acc[2] = fmaf(cf, f1.x, acc[2]); acc[3] = fmaf(cf, f1.y, acc[3]);
            acc[4] = fmaf(cf, f2.x, acc[4]); acc[5] = fmaf(cf, f2.y, acc[5]);
            acc[6] = fmaf(cf, f3.x, acc[6]); acc[7] = fmaf(cf, f3.y, acc[7]);
        }
    }
    if (do_relu) {
#pragma unroll
        for (int j = 0; j < 8; j++) acc[j] = fmaxf(acc[j], 0.0f);
    }
    if (outH) {
        uint4 u;
        *(__half2*)&u.x = __floats2half2_rn(acc[0], acc[1]);
        *(__half2*)&u.y = __floats2half2_rn(acc[2], acc[3]);
        *(__half2*)&u.z = __floats2half2_rn(acc[4], acc[5]);
        *(__half2*)&u.w = __floats2half2_rn(acc[6], acc[7]);
        *(uint4*)(outH + (size_t)d * dout + c8) = u;
    } else {
        float* o = outF + (size_t)d * dout + c8;
        *(float4*)o       = make_float4(acc[0], acc[1], acc[2], acc[3]);
        *(float4*)(o + 4) = make_float4(acc[4], acc[5], acc[6], acc[7]);
    }
}

// ---------------- edge-score MLP (pos + neg in one launch) ------------------
__global__ __launch_bounds__(128) void edge_mlp_kernel(
    const float* __restrict__ h,
    const int* __restrict__ pos_src, const int* __restrict__ pos_dst,
    const int* __restrict__ neg_src, const int* __restrict__ neg_dst,
    const float* __restrict__ Wp1, const float* __restrict__ bp1,
    const float* __restrict__ Wp2, const float* __restrict__ bp2,
    float* __restrict__ out, int EP) {
    __shared__ float sW1[128 * 64];
    __shared__ float sb1[64];
    __shared__ float sW2[64];
    __shared__ float sb2;
    for (int i = threadIdx.x; i < 128 * 64; i += 128) sW1[i] = Wp1[i];
    if (threadIdx.x < 64) {
        sb1[threadIdx.x] = bp1[threadIdx.x];
        sW2[threadIdx.x] = Wp2[threadIdx.x];
    }
    if (threadIdx.x == 0) sb2 = bp2[0];
    __syncthreads();

    int e = blockIdx.x * 128 + threadIdx.x;
    if (e >= 2 * EP) return;
    int s, d;
    if (e < EP) { s = pos_src[e]; d = pos_dst[e]; }
    else        { s = neg_src[e - EP]; d = neg_dst[e - EP]; }

    float hid[64];
#pragma unroll
    for (int j = 0; j < 64; j++) hid[j] = sb1[j];

    const float* hs = h + (size_t)s * 64;
#pragma unroll 4
    for (int k = 0; k < 64; k++) {
        float zk = __ldg(hs + k);
        const float* w = &sW1[k * 64];
#pragma unroll
        for (int j = 0; j < 64; j++) hid[j] += zk * w[j];
    }
    const float* hd = h + (size_t)d * 64;
#pragma unroll 4
    for (int k = 0; k < 64; k++) {
        float zk = __ldg(hd + k);
        const float* w = &sW1[(64 + k) * 64];
#pragma unroll
        for (int j = 0; j < 64; j++) hid[j] += zk * w[j];
    }

    float sc = sb2;
#pragma unroll
    for (int j = 0; j < 64; j++) sc += fmaxf(hid[j], 0.0f) * sW2[j];
    out[e] = sc;
}

// ---------------- entry -----------------------------------------------------
extern "C" void kernel_launch(void* const* d_in, const int* in_sizes, int n_in,
                              void* d_out, int out_size) {
    const float* x       = (const float*)d_in[0];
    const int*   rel_src = (const int*)d_in[1];
    const int*   rel_dst = (const int*)d_in[2];
    const int*   pos_src = (const int*)d_in[3];
    const int*   pos_dst = (const int*)d_in[4];
    const int*   neg_src = (const int*)d_in[5];
    const int*   neg_dst = (const int*)d_in[6];
    const float* W0 = (const float*)d_in[7];
    const float* b0 = (const float*)d_in[8];
    const float* W1 = (const float*)d_in[9];
    const float* b1 = (const float*)d_in[10];
    const float* W2 = (const float*)d_in[11];
    const float* b2 = (const float*)d_in[12];
    const float* W3 = (const float*)d_in[13];
    const float* b3 = (const float*)d_in[14];
    const float* Wp1 = (const float*)d_in[15];
    const float* bp1 = (const float*)d_in[16];
    const float* Wp2 = (const float*)d_in[17];
    const float* bp2 = (const float*)d_in[18];
    float* out = (float*)d_out;

    const int N  = in_sizes[0] / 512;
    const int E  = in_sizes[1] / RREL;
    const int EP = in_sizes[3];

    cudaFuncSetAttribute(gemm_f16_kernel,
                         cudaFuncAttributeMaxDynamicSharedMemorySize, GEMM_SMEM_BYTES);

    float *hB, *sn, *dn, *ecoef;
    __half *xh, *hH, *Bch, *hrh;
    int *off, *cur, *esrc;
    cudaGetSymbolAddress((void**)&hB,    g_hB);
    cudaGetSymbolAddress((void**)&hrh,   g_hrh);
    cudaGetSymbolAddress((void**)&xh,    g_xh);
    cudaGetSymbolAddress((void**)&hH,    g_hH);
    cudaGetSymbolAddress((void**)&Bch,   g_Bch);
    cudaGetSymbolAddress((void**)&sn,    g_sn);
    cudaGetSymbolAddress((void**)&dn,    g_dn);
    cudaGetSymbolAddress((void**)&off,   g_off);
    cudaGetSymbolAddress((void**)&cur,   g_cur);
    cudaGetSymbolAddress((void**)&esrc,  g_esrc);
    cudaGetSymbolAddress((void**)&ecoef, g_ecoef);

    __half* Bc0 = Bch;
    __half* Bc1 = Bc0 + RREL * 512 * 512;
    __half* Bc2 = Bc1 + RREL * 512 * 256;
    __half* Bc3 = Bc2 + RREL * 256 * 128;

    // launch 0: round input
    { int n = N * 512; round_half_kernel<<<(n + 255) / 256, 256>>>(x, xh, n); }
    // launch 1: pack W0
    { int t = RREL * 512 * 512; pack_w_kernel<<<(t + 255) / 256, 256>>>(W0, Bc0, 512, 512); }
    // launch 2: zero degree arrays
    { int rn = RREL * N; zero2_kernel<<<(rn + 255) / 256, 256>>>(sn, dn, rn); }
    // launch 3: layer-0 GEMM  (ncu captures this one)
    {
        int Ncat = RREL * 512;
        dim3 grid((Ncat + BN - 1) / BN, (N + BM - 1) / BM);
        gemm_f16_kernel<<<grid, 256, GEMM_SMEM_BYTES>>>(xh, Bc0, hrh, N, 512, Ncat);
    }
    // graph prep
    { int re = RREL * E; deg_kernel<<<(re + 255) / 256, 256>>>(rel_src, rel_dst, sn, dn, E, N); }
    scan_kernel<<<RREL, 1024>>>(dn, off, cur, N);
    { int re = RREL * E; fill_kernel<<<(re + 255) / 256, 256>>>(rel_src, rel_dst, sn, dn,
                                                                cur, esrc, ecoef, E, N); }
    // pack remaining weights
    { int t = RREL * 512 * 256; pack_w_kernel<<<(t + 255) / 256, 256>>>(W1, Bc1, 512, 256); }
    { int t = RREL * 256 * 128; pack_w_kernel<<<(t + 255) / 256, 256>>>(W2, Bc2, 256, 128); }
    { int t = RREL * 128 * 64;  pack_w_kernel<<<(t + 255) / 256, 256>>>(W3, Bc3, 128, 64); }

    // layer-0 gather -> hH (fp16, relu)
    {
        int dout = 512, total = N * (dout >> 3);
        gather_kernel<<<(total + 255) / 256, 256>>>(hrh, off, esrc, ecoef, b0,
                                                    hH, nullptr, N, E, dout, 1);
    }
    // layers 1..3
    struct { const __half* Bc; const float* bl; int din, dout, relu; }
        L[3] = {{Bc1, b1, 512, 256, 1}, {Bc2, b2, 256, 128, 1}, {Bc3, b3, 128, 64, 0}};
    for (int l = 0; l < 3; l++) {
        int din = L[l].din, dout = L[l].dout;
        int Ncat = RREL * dout;
        dim3 grid((Ncat + BN - 1) / BN, (N + BM - 1) / BM);
        gemm_f16_kernel<<<grid, 256, GEMM_SMEM_BYTES>>>(hH, L[l].Bc, hrh, N, din, Ncat);
        int total = N * (dout >> 3);
        if (l < 2)
            gather_kernel<<<(total + 255) / 256, 256>>>(hrh, off, esrc, ecoef, L[l].bl,
                                                        hH, nullptr, N, E, dout, 1);
        else
            gather_kernel<<<(total + 255) / 256, 256>>>(hrh, off, esrc, ecoef, L[l].bl,
                                                        nullptr, hB, N, E, dout, 0);
    }

    // edge-score MLP: pos + neg in one launch
    edge_mlp_kernel<<<(2 * EP + 127) / 128, 128>>>(hB, pos_src, pos_dst, neg_src, neg_dst,
                                                   Wp1, bp1, Wp2, bp2, out, EP);
}

// round 14
// speedup vs baseline: 1.2808x; 1.2808x over previous
#include <cuda_runtime.h>
#include <cuda_fp16.h>
#include <cstdint>
#include <math.h>

#define NNODES 50000
#define RREL 3
#define EEDGE 50000
#define WTOTAL 1302528  // 3*(512*512 + 512*256 + 256*128 + 128*64)

// ---------------- scratch (device globals; no allocation allowed) ----------
__device__ __half g_hrh[(size_t)NNODES * 1536];   // fp16 GEMM out [N, 3*dout] / UV
__device__ __half g_xh[(size_t)NNODES * 512];     // fp16 layer-0 A
__device__ __half g_hH[(size_t)NNODES * 512];     // fp16 A for layers 1..3
__device__ __half g_hF[(size_t)NNODES * 64];      // fp16 final node embedding
__device__ __half g_Bch[WTOTAL];                  // fp16 packed weights [K, 3*dout]
__device__ __half g_Bp[64 * 128];                 // fp16 packed Wp1 [64, 128]
__device__ float  g_sn[RREL * NNODES];            // raw out-degrees
__device__ float  g_dn[RREL * NNODES];            // raw in-degrees
__device__ int    g_off[RREL * (NNODES + 1)];     // CSR offsets by dst
__device__ int    g_cur[RREL * NNODES];           // fill cursors
__device__ int    g_esrc[RREL * EEDGE];           // CSR edge src
__device__ float  g_ecoef[RREL * EEDGE];          // CSR edge coef

// ---------------- helpers ---------------------------------------------------
__device__ __forceinline__ uint32_t smem_u32(const void* p) {
    uint32_t a;
    asm("{ .reg .u64 t; cvta.to.shared.u64 t, %1; cvt.u32.u64 %0, t; }" : "=r"(a) : "l"(p));
    return a;
}
__device__ __forceinline__ void cp_async16(uint32_t dst, const void* src, bool pred) {
    int b = pred ? 16 : 0;
    asm volatile("cp.async.cg.shared.global [%0], [%1], 16, %2;\n"
                 :: "r"(dst), "l"(src), "r"(b));
}
#define CP_COMMIT() asm volatile("cp.async.commit_group;\n" ::: "memory")
#define CP_WAIT(n)  asm volatile("cp.async.wait_group %0;\n" :: "n"(n) : "memory")

__device__ __forceinline__ void ldsm_x4(uint32_t& r0, uint32_t& r1, uint32_t& r2,
                                        uint32_t& r3, uint32_t addr) {
    asm volatile("ldmatrix.sync.aligned.m8n8.x4.shared.b16 {%0,%1,%2,%3}, [%4];"
                 : "=r"(r0), "=r"(r1), "=r"(r2), "=r"(r3) : "r"(addr));
}
__device__ __forceinline__ void ldsm_x4_t(uint32_t& r0, uint32_t& r1, uint32_t& r2,
                                          uint32_t& r3, uint32_t addr) {
    asm volatile("ldmatrix.sync.aligned.m8n8.x4.trans.shared.b16 {%0,%1,%2,%3}, [%4];"
                 : "=r"(r0), "=r"(r1), "=r"(r2), "=r"(r3) : "r"(addr));
}
__device__ __forceinline__ void mma_f16(float c[4], const uint32_t a[4], const uint32_t b[2]) {
    asm volatile(
        "mma.sync.aligned.m16n8k16.row.col.f32.f16.f16.f32 "
        "{%0,%1,%2,%3}, {%4,%5,%6,%7}, {%8,%9}, {%0,%1,%2,%3};\n"
        : "+f"(c[0]), "+f"(c[1]), "+f"(c[2]), "+f"(c[3])
        : "r"(a[0]), "r"(a[1]), "r"(a[2]), "r"(a[3]), "r"(b[0]), "r"(b[1]));
}

// ---------------- small utility kernels ------------------------------------
__global__ void zero2_kernel(float* __restrict__ a, float* __restrict__ b, int n) {
    int i = blockIdx.x * blockDim.x + threadIdx.x;
    if (i < n) { a[i] = 0.0f; b[i] = 0.0f; }
}

__global__ void round_half_kernel(const float* __restrict__ in, __half* __restrict__ out, int n) {
    int i = blockIdx.x * blockDim.x + threadIdx.x;
    if (i < n) out[i] = __float2half_rn(in[i]);
}

// pack W[r, k, c] -> Bch[k, r*dout + c] fp16. [K, Ncat] row-major.
__global__ void pack_w_kernel(const float* __restrict__ W, __half* __restrict__ out,
                              int din, int dout) {
    int i = blockIdx.x * blockDim.x + threadIdx.x;
    int Ncat = RREL * dout;
    int total = din * Ncat;
    if (i >= total) return;
    int k = i / Ncat;
    int n = i - k * Ncat;
    int r = n / dout;
    int c = n - r * dout;
    out[i] = __float2half_rn(W[((size_t)r * din + k) * dout + c]);
}

// pack Wp1[128,64] -> Bp[k, c] (k<64): c<64 -> Wp1[k][c]; else Wp1[64+k][c-64]
__global__ void pack_wp_kernel(const float* __restrict__ Wp1, __half* __restrict__ out) {
    int i = blockIdx.x * blockDim.x + threadIdx.x;
    if (i >= 64 * 128) return;
    int k = i >> 7;
    int c = i & 127;
    float v = (c < 64) ? Wp1[k * 64 + c] : Wp1[(64 + k) * 64 + (c - 64)];
    out[i] = __float2half_rn(v);
}

__global__ void deg_kernel(const int* __restrict__ src, const int* __restrict__ dst,
                           float* __restrict__ outdeg, float* __restrict__ indeg,
                           int E, int N) {
    int i = blockIdx.x * blockDim.x + threadIdx.x;
    if (i < RREL * E) {
        int r = i / E;
        atomicAdd(&outdeg[r * N + src[i]], 1.0f);
        atomicAdd(&indeg[r * N + dst[i]], 1.0f);
    }
}

// per-relation exclusive prefix scan, shuffle-based. 3 blocks x 1024.
__global__ void scan_kernel(const float* __restrict__ dn, int* __restrict__ off,
                            int* __restrict__ cur, int N) {
    int r = blockIdx.x;
    const float* c = dn + r * N;
    int* o = off + r * (N + 1);
    int* q = cur + r * N;
    int tid = threadIdx.x;
    int lane = tid & 31;
    int wid = tid >> 5;
    __shared__ int wsum[32];
    __shared__ int carry_s;
    if (tid == 0) carry_s = 0;
    __syncthreads();
    for (int base = 0; base < N; base += 1024) {
        int i = base + tid;
        int v = (i < N) ? (int)c[i] : 0;
        int x = v;
#pragma unroll
        for (int d = 1; d < 32; d <<= 1) {
            int t = __shfl_up_sync(0xFFFFFFFF, x, d);
            if (lane >= d) x += t;
        }
        if (lane == 31) wsum[wid] = x;
        __syncthreads();
        if (wid == 0) {
            int s = wsum[lane];
#pragma unroll
            for (int d = 1; d < 32; d <<= 1) {
                int t = __shfl_up_sync(0xFFFFFFFF, s, d);
                if (lane >= d) s += t;
            }
            wsum[lane] = s;
        }
        __syncthreads();
        int warpoff = (wid > 0) ? wsum[wid - 1] : 0;
        int excl = carry_s + warpoff + x - v;
        if (i < N) { o[i] = excl; q[i] = excl; }
        int total = wsum[31];
        __syncthreads();
        if (tid == 0) carry_s += total;
        __syncthreads();
    }
    if (tid == 0) o[N] = carry_s;
}

// scatter edges into CSR slots; coef computed inline from raw degrees
__global__ void fill_kernel(const int* __restrict__ src, const int* __restrict__ dst,
                            const float* __restrict__ sn, const float* __restrict__ dn,
                            int* __restrict__ cur, int* __restrict__ esrc,
                            float* __restrict__ ecoef, int E, int N) {
    int i = blockIdx.x * blockDim.x + threadIdx.x;
    if (i >= RREL * E) return;
    int r = i / E;
    int s = src[i], d = dst[i];
    int pos = atomicAdd(&cur[r * N + d], 1);
    esrc[r * E + pos] = s;
    ecoef[r * E + pos] = rsqrtf(fmaxf(sn[r * N + s], 1.0f)) *
                         rsqrtf(fmaxf(dn[r * N + d], 1.0f));
}

// ---------------- fp16 tensor-core GEMM, BK=64, 3-stage cp.async ------------
// (R9 config: validated at 49.3% tensor = crossbar ceiling, 2 CTAs/SM)
#define BM 128
#define BN 128
#define BK 64
#define STAGES 3
#define ASTR 72     // halfs per A smem row (144 B)
#define BSTR 136    // halfs per B smem row (272 B)
#define A_STAGE_H (BM * ASTR)
#define B_STAGE_H (BK * BSTR)
#define STAGE_HALFS (A_STAGE_H + B_STAGE_H)
#define GEMM_SMEM_BYTES (STAGES * STAGE_HALFS * 2)   // 107520

__device__ __forceinline__ void issue_stage_loads(
    uint32_t sAs, uint32_t sBs,
    const __half* __restrict__ A, const __half* __restrict__ B,
    int M, int K, int Nc, int rowBase, int colBase, int k0, int tid) {
#pragma unroll
    for (int t = 0; t < 4; t++) {
        int i  = tid + t * 256;
        int r  = i >> 3;
        int kc = (i & 7) << 3;
        int gr = rowBase + r;
        cp_async16(sAs + (uint32_t)(r * ASTR + kc) * 2,
                   A + (size_t)gr * K + k0 + kc, gr < M);
    }
#pragma unroll
    for (int t = 0; t < 4; t++) {
        int i  = tid + t * 256;
        int kr = i >> 4;
        int nc = (i & 15) << 3;
        cp_async16(sBs + (uint32_t)(kr * BSTR + nc) * 2,
                   B + (size_t)(k0 + kr) * Nc + colBase + nc, colBase + nc < Nc);
    }
}

__global__ void __launch_bounds__(256, 2) gemm_f16_kernel(
    const __half* __restrict__ A, const __half* __restrict__ B,
    __half* __restrict__ C, int M, int K, int Nc) {
    extern __shared__ __half smemh[];
    uint32_t sA[STAGES], sB[STAGES];
#pragma unroll
    for (int s = 0; s < STAGES; s++) {
        sA[s] = smem_u32(smemh + (size_t)s * STAGE_HALFS);
        sB[s] = sA[s] + A_STAGE_H * 2;
    }

    const int tid    = threadIdx.x;
    const int warpId = tid >> 5;
    const int lane   = tid & 31;
    const int g      = lane >> 2;
    const int tig    = lane & 3;
    const int wm     = warpId & 3;
    const int wn     = warpId >> 2;
    const int rowBase = blockIdx.y * BM;
    const int colBase = blockIdx.x * BN;

    float acc[2][8][4];
#pragma unroll
    for (int mm = 0; mm < 2; mm++)
#pragma unroll
        for (int nn = 0; nn < 8; nn++)
#pragma unroll
            for (int i = 0; i < 4; i++) acc[mm][nn][i] = 0.0f;

    const int a_row = (lane & 15);
    const int a_sel = (lane >> 4) << 3;
    const int b_krow = (lane & 7) + (((lane >> 3) & 1) << 3);
    const int b_nsel = (lane >> 4) << 3;

    const int nk = K >> 6;
    issue_stage_loads(sA[0], sB[0], A, B, M, K, Nc, rowBase, colBase, 0, tid);
    CP_COMMIT();
    if (nk > 1) {
        issue_stage_loads(sA[1], sB[1], A, B, M, K, Nc, rowBase, colBase, 64, tid);
    }
    CP_COMMIT();

    int buf = 0;
    for (int i = 0; i < nk; i++) {
        if (i + 1 < nk) { CP_WAIT(1); } else { CP_WAIT(0); }
        __syncthreads();

        if (i + 2 < nk) {
            int nb = buf + 2; if (nb >= STAGES) nb -= STAGES;
            issue_stage_loads(sA[nb], sB[nb], A, B, M, K, Nc,
                              rowBase, colBase, (i + 2) << 6, tid);
            CP_COMMIT();
        }

        uint32_t sa = sA[buf], sb = sB[buf];
#pragma unroll
        for (int ks = 0; ks < BK; ks += 16) {
            uint32_t a[2][4], b[8][2];
#pragma unroll
            for (int mm = 0; mm < 2; mm++) {
                uint32_t ad = sa + (uint32_t)((wm * 32 + mm * 16 + a_row) * ASTR + ks + a_sel) * 2;
                ldsm_x4(a[mm][0], a[mm][1], a[mm][2], a[mm][3], ad);
            }
#pragma unroll
            for (int np = 0; np < 4; np++) {
                uint32_t bd = sb + (uint32_t)((ks + b_krow) * BSTR + wn * 64 + np * 16 + b_nsel) * 2;
                uint32_t t0, t1, t2, t3;
                ldsm_x4_t(t0, t1, t2, t3, bd);
                b[np * 2][0] = t0; b[np * 2][1] = t1;
                b[np * 2 + 1][0] = t2; b[np * 2 + 1][1] = t3;
            }
#pragma unroll
            for (int mm = 0; mm < 2; mm++)
#pragma unroll
                for (int nn = 0; nn < 8; nn++)
                    mma_f16(acc[mm][nn], a[mm], b[nn]);
        }
        buf++; if (buf >= STAGES) buf -= STAGES;
    }

#pragma unroll
    for (int mm = 0; mm < 2; mm++) {
        int r0 = rowBase + wm * 32 + mm * 16 + g;
#pragma unroll
        for (int nn = 0; nn < 8; nn++) {
            int c = colBase + wn * 64 + nn * 8 + tig * 2;
            if (c < Nc) {
                if (r0 < M)
                    *(__half2*)(C + (size_t)r0 * Nc + c) =
                        __floats2half2_rn(acc[mm][nn][0], acc[mm][nn][1]);
                if (r0 + 8 < M)
                    *(__half2*)(C + (size_t)(r0 + 8) * Nc + c) =
                        __floats2half2_rn(acc[mm][nn][2], acc[mm][nn][3]);
            }
        }
    }
}

// ---------------- CSR gather: bias + aggregate + (relu) + fp16 write --------
__global__ void gather_kernel(const __half* __restrict__ hr,
                              const int* __restrict__ off, const int* __restrict__ esrc,
                              const float* __restrict__ ecoef,
                              const float* __restrict__ b,
                              __half* __restrict__ outH,
                              int N, int E, int dout, int do_relu) {
    int dout8 = dout >> 3;
    int idx = blockIdx.x * blockDim.x + threadIdx.x;
    if (idx >= N * dout8) return;
    int d  = idx / dout8;
    int c8 = (idx - d * dout8) << 3;
    int Ncat = RREL * dout;

    float acc[8];
#pragma unroll
    for (int j = 0; j < 8; j++)
        acc[j] = b[c8 + j] + b[dout + c8 + j] + b[2 * dout + c8 + j];

#pragma unroll
    for (int r = 0; r < RREL; r++) {
        int beg = off[r * (N + 1) + d];
        int end = off[r * (N + 1) + d + 1];
        for (int i = beg; i < end; i++) {
            int s = esrc[r * E + i];
            float cf = ecoef[r * E + i];
            const __half* p = hr + (size_t)s * Ncat + r * dout + c8;
            uint4 u = *(const uint4*)p;
            __half2 h0 = *(__half2*)&u.x, h1 = *(__half2*)&u.y;
            __half2 h2 = *(__half2*)&u.z, h3 = *(__half2*)&u.w;
            float2 f0 = __half22float2(h0), f1 = __half22float2(h1);
            float2 f2 = __half22float2(h2), f3 = __half22float2(h3);
            acc[0] = fmaf(cf, f0.x, acc[0]); acc[1] = fmaf(cf, f0.y, acc[1]);
            acc[2] = fmaf(cf, f1.x, acc[2]); acc[3] = fmaf(cf, f1.y, acc[3]);
            acc[4] = fmaf(cf, f2.x, acc[4]); acc[5] = fmaf(cf, f2.y, acc[5]);
            acc[6] = fmaf(cf, f3.x, acc[6]); acc[7] = fmaf(cf, f3.y, acc[7]);
        }
    }
    if (do_relu) {
#pragma unroll
        for (int j = 0; j < 8; j++) acc[j] = fmaxf(acc[j], 0.0f);
    }
    uint4 u;
    *(__half2*)&u.x = __floats2half2_rn(acc[0], acc[1]);
    *(__half2*)&u.y = __floats2half2_rn(acc[2], acc[3]);
    *(__half2*)&u.z = __floats2half2_rn(acc[4], acc[5]);
    *(__half2*)&u.w = __floats2half2_rn(acc[6], acc[7]);
    *(uint4*)(outH + (size_t)d * dout + c8) = u;
}

// ---------------- edge score: relu(U[s]+V[d]+b) . Wp2 + bp2 -----------------
// UV[n, 0:64] = h[n] @ Wp1[:64];  UV[n, 64:128] = h[n] @ Wp1[64:]
__global__ __launch_bounds__(256) void edge_score_kernel(
    const __half* __restrict__ UV,
    const int* __restrict__ pos_src, const int* __restrict__ pos_dst,
    const int* __restrict__ neg_src, const int* __restrict__ neg_dst,
    const float* __restrict__ bp1, const float* __restrict__ Wp2,
    const float* __restrict__ bp2, float* __restrict__ out, int EP) {
    __shared__ float sb1[64];
    __shared__ float sW2[64];
    __shared__ float sb2;
    if (threadIdx.x < 64) {
        sb1[threadIdx.x] = bp1[threadIdx.x];
        sW2[threadIdx.x] = Wp2[threadIdx.x];
    }
    if (threadIdx.x == 0) sb2 = bp2[0];
    __syncthreads();

    int e = blockIdx.x * 256 + threadIdx.x;
    if (e >= 2 * EP) return;
    int s, d;
    if (e < EP) { s = pos_src[e]; d = pos_dst[e]; }
    else        { s = neg_src[e - EP]; d = neg_dst[e - EP]; }

    const uint4* us = (const uint4*)(UV + (size_t)s * 128);        // U part
    const uint4* vd = (const uint4*)(UV + (size_t)d * 128 + 64);   // V part
    float sc = sb2;
#pragma unroll
    for (int q = 0; q < 8; q++) {
        uint4 uu = us[q];
        uint4 vv = vd[q];
        const __half2* uh = (const __half2*)&uu;
        const __half2* vh = (const __half2*)&vv;
#pragma unroll
        for (int t = 0; t < 4; t++) {
            float2 fu = __half22float2(uh[t]);
            float2 fv = __half22float2(vh[t]);
            int j = q * 8 + t * 2;
            float h0 = fmaxf(fu.x + fv.x + sb1[j], 0.0f);
            float h1 = fmaxf(fu.y + fv.y + sb1[j + 1], 0.0f);
            sc = fmaf(h0, sW2[j], sc);
            sc = fmaf(h1, sW2[j + 1], sc);
        }
    }
    out[e] = sc;
}

// ---------------- entry -----------------------------------------------------
extern "C" void kernel_launch(void* const* d_in, const int* in_sizes, int n_in,
                              void* d_out, int out_size) {
    const float* x       = (const float*)d_in[0];
    const int*   rel_src = (const int*)d_in[1];
    const int*   rel_dst = (const int*)d_in[2];
    const int*   pos_src = (const int*)d_in[3];
    const int*   pos_dst = (const int*)d_in[4];
    const int*   neg_src = (const int*)d_in[5];
    const int*   neg_dst = (const int*)d_in[6];
    const float* W0 = (const float*)d_in[7];
    const float* b0 = (const float*)d_in[8];
    const float* W1 = (const float*)d_in[9];
    const float* b1 = (const float*)d_in[10];
    const float* W2 = (const float*)d_in[11];
    const float* b2 = (const float*)d_in[12];
    const float* W3 = (const float*)d_in[13];
    const float* b3 = (const float*)d_in[14];
    const float* Wp1 = (const float*)d_in[15];
    const float* bp1 = (const float*)d_in[16];
    const float* Wp2 = (const float*)d_in[17];
    const float* bp2 = (const float*)d_in[18];
    float* out = (float*)d_out;

    const int N  = in_sizes[0] / 512;
    const int E  = in_sizes[1] / RREL;
    const int EP = in_sizes[3];

    cudaFuncSetAttribute(gemm_f16_kernel,
                         cudaFuncAttributeMaxDynamicSharedMemorySize, GEMM_SMEM_BYTES);

    float *sn, *dn, *ecoef;
    __half *xh, *hH, *hF, *Bch, *Bp, *hrh;
    int *off, *cur, *esrc;
    cudaGetSymbolAddress((void**)&hrh,   g_hrh);
    cudaGetSymbolAddress((void**)&xh,    g_xh);
    cudaGetSymbolAddress((void**)&hH,    g_hH);
    cudaGetSymbolAddress((void**)&hF,    g_hF);
    cudaGetSymbolAddress((void**)&Bch,   g_Bch);
    cudaGetSymbolAddress((void**)&Bp,    g_Bp);
    cudaGetSymbolAddress((void**)&sn,    g_sn);
    cudaGetSymbolAddress((void**)&dn,    g_dn);
    cudaGetSymbolAddress((void**)&off,   g_off);
    cudaGetSymbolAddress((void**)&cur,   g_cur);
    cudaGetSymbolAddress((void**)&esrc,  g_esrc);
    cudaGetSymbolAddress((void**)&ecoef, g_ecoef);

    __half* Bc0 = Bch;
    __half* Bc1 = Bc0 + RREL * 512 * 512;
    __half* Bc2 = Bc1 + RREL * 512 * 256;
    __half* Bc3 = Bc2 + RREL * 256 * 128;

    // launch 0: round input
    { int n = N * 512; round_half_kernel<<<(n + 255) / 256, 256>>>(x, xh, n); }
    // launch 1: pack W0
    { int t = RREL * 512 * 512; pack_w_kernel<<<(t + 255) / 256, 256>>>(W0, Bc0, 512, 512); }
    // launch 2: zero degree arrays
    { int rn = RREL * N; zero2_kernel<<<(rn + 255) / 256, 256>>>(sn, dn, rn); }
    // launch 3: layer-0 GEMM (ncu captures this one)
    {
        int Ncat = RREL * 512;
        dim3 grid((Ncat + BN - 1) / BN, (N + BM - 1) / BM);
        gemm_f16_kernel<<<grid, 256, GEMM_SMEM_BYTES>>>(xh, Bc0, hrh, N, 512, Ncat);
    }
    // graph prep
    { int re = RREL * E; deg_kernel<<<(re + 255) / 256, 256>>>(rel_src, rel_dst, sn, dn, E, N); }
    scan_kernel<<<RREL, 1024>>>(dn, off, cur, N);
    { int re = RREL * E; fill_kernel<<<(re + 255) / 256, 256>>>(rel_src, rel_dst, sn, dn,
                                                                cur, esrc, ecoef, E, N); }
    // pack remaining weights + prediction weights
    { int t = RREL * 512 * 256; pack_w_kernel<<<(t + 255) / 256, 256>>>(W1, Bc1, 512, 256); }
    { int t = RREL * 256 * 128; pack_w_kernel<<<(t + 255) / 256, 256>>>(W2, Bc2, 256, 128); }
    { int t = RREL * 128 * 64;  pack_w_kernel<<<(t + 255) / 256, 256>>>(W3, Bc3, 128, 64); }
    pack_wp_kernel<<<(64 * 128 + 255) / 256, 256>>>(Wp1, Bp);

    // layer-0 gather -> hH (fp16, relu)
    {
        int dout = 512, total = N * (dout >> 3);
        gather_kernel<<<(total + 255) / 256, 256>>>(hrh, off, esrc, ecoef, b0,
                                                    hH, N, E, dout, 1);
    }
    // layers 1..3
    struct { const __half* Bc; const float* bl; int din, dout, relu; __half* dst; }
        L[3] = {{Bc1, b1, 512, 256, 1, hH}, {Bc2, b2, 256, 128, 1, hH},
                {Bc3, b3, 128, 64, 0, hF}};
    for (int l = 0; l < 3; l++) {
        int din = L[l].din, dout = L[l].dout;
        int Ncat = RREL * dout;
        dim3 grid((Ncat + BN - 1) / BN, (N + BM - 1) / BM);
        gemm_f16_kernel<<<grid, 256, GEMM_SMEM_BYTES>>>(hH, L[l].Bc, hrh, N, din, Ncat);
        int total = N * (dout >> 3);
        gather_kernel<<<(total + 255) / 256, 256>>>(hrh, off, esrc, ecoef, L[l].bl,
                                                    L[l].dst, N, E, dout, L[l].relu);
    }

    // UV GEMM: [N,64] @ [64,128] -> UV in hrh
    {
        dim3 grid(1, (N + BM - 1) / BM);
        gemm_f16_kernel<<<grid, 256, GEMM_SMEM_BYTES>>>(hF, Bp, hrh, N, 64, 128);
    }

    // edge scores: pos + neg in one launch
    edge_score_kernel<<<(2 * EP + 255) / 256, 256>>>(hrh, pos_src, pos_dst, neg_src, neg_dst,
                                                     bp1, Wp2, bp2, out, EP);
}